// round 5
// baseline (speedup 1.0000x reference)
#include <cuda_runtime.h>
#include <cuda_fp16.h>
#include <math.h>

#define HID   1024
#define G4    4096
#define NB    32
#define NT    100
#define IND   132
#define KP    192
#define OUTW  13200   // 100*132
#define ASTR  72      // smem row stride in halves (64+8 pad)

// ---------------- persistent device scratch ----------------
__device__ __half g_Wh[5][G4][HID];   // hi: W_hh1, W_ih2, W_hh2, W_ih3, W_hh3
__device__ __half g_Wl[5][G4][HID];   // lo
__device__ __half g_Mwh[G4][HID];     // Mw = W_ih1 @ W_dec  (hi)
__device__ __half g_Mwl[G4][HID];
__device__ __half g_W1h[G4][KP];      // W_ih1 padded 132->192
__device__ __half g_W1l[G4][KP];
__device__ __half g_xh[NT][NB][KP];   // frames padded, hi
__device__ __half g_xl[NT][NB][KP];
__device__ float  g_hf[2][3][NB][HID];
__device__ __half g_hh[2][3][NB][HID];
__device__ __half g_hl[2][3][NB][HID];
__device__ float  g_c[3][NB][HID];
__device__ float  g_bs[3][G4];        // b_ih + b_hh
__device__ float  g_bsM[G4];          // g_bs[0] + W_ih1@b_dec

// ---------------- asm helpers ----------------
__device__ __forceinline__ unsigned sptr(const void* p) {
    return (unsigned)__cvta_generic_to_shared(p);
}
__device__ __forceinline__ void cpa16(__half* s, const __half* g) {
    asm volatile("cp.async.cg.shared.global [%0], [%1], 16;" :: "r"(sptr(s)), "l"(g));
}
__device__ __forceinline__ void cpcommit() { asm volatile("cp.async.commit_group;"); }
__device__ __forceinline__ void cpwait0()  { asm volatile("cp.async.wait_group 0;"); }
__device__ __forceinline__ void cpwait1()  { asm volatile("cp.async.wait_group 1;"); }

__device__ __forceinline__ void ldmA4(unsigned a[4], unsigned addr) {
    asm volatile("ldmatrix.sync.aligned.m8n8.x4.shared.b16 {%0,%1,%2,%3}, [%4];"
                 : "=r"(a[0]), "=r"(a[1]), "=r"(a[2]), "=r"(a[3]) : "r"(addr));
}
__device__ __forceinline__ void ldmB2(unsigned b[2], unsigned addr) {
    asm volatile("ldmatrix.sync.aligned.m8n8.x2.shared.b16 {%0,%1}, [%2];"
                 : "=r"(b[0]), "=r"(b[1]) : "r"(addr));
}
__device__ __forceinline__ void mma16816(float c[4], const unsigned a[4], const unsigned b[2]) {
    asm volatile("mma.sync.aligned.m16n8k16.row.col.f32.f16.f16.f32 "
                 "{%0,%1,%2,%3}, {%4,%5,%6,%7}, {%8,%9}, {%0,%1,%2,%3};"
                 : "+f"(c[0]), "+f"(c[1]), "+f"(c[2]), "+f"(c[3])
                 : "r"(a[0]), "r"(a[1]), "r"(a[2]), "r"(a[3]), "r"(b[0]), "r"(b[1]));
}
__device__ __forceinline__ float sigm(float x) { return 1.0f / (1.0f + __expf(-x)); }
__device__ __forceinline__ int growf(int n, int j0) { return ((n >> 5) << 10) + j0 + (n & 31); }

// ---------------- GEMM core: acc += A[32,K] * Brows^T, N=128 gathered rows ----------------
// smem layout (halves): sAh[2][32][72] @0, sAl @4608, sBh[2][128][72] @9216, sBl @27648
__device__ __forceinline__ void gemm2(
    float acc[2][2][4], __half* sm,
    const __half* __restrict__ Ah, const __half* __restrict__ Al, int aStr,
    const __half* __restrict__ Bh, const __half* __restrict__ Bl, int bStr,
    int j0, int K, int tid)
{
    __half* sAh = sm;
    __half* sAl = sm + 4608;
    __half* sBh = sm + 9216;
    __half* sBl = sm + 27648;
    const int lane = tid & 31, w = tid >> 5;
    const int arow = tid >> 3, ako = (tid & 7) << 3;
    const int nst = K >> 6;

    // prologue: stage 0 -> buffer 0
    cpa16(sAh + arow * ASTR + ako, Ah + arow * aStr + ako);
    cpa16(sAl + arow * ASTR + ako, Al + arow * aStr + ako);
#pragma unroll
    for (int i = 0; i < 4; i++) {
        int c = tid + (i << 8);
        int br = c >> 3, bko = (c & 7) << 3;
        int g = growf(br, j0);
        cpa16(sBh + br * ASTR + bko, Bh + g * bStr + bko);
        cpa16(sBl + br * ASTR + bko, Bl + g * bStr + bko);
    }
    cpcommit();

    for (int s = 0; s < nst; s++) {
        if (s + 1 < nst) {
            const int k0 = (s + 1) << 6;
            const int ab = ((s + 1) & 1) * 2304;
            const int bb = ((s + 1) & 1) * 9216;
            cpa16(sAh + ab + arow * ASTR + ako, Ah + arow * aStr + k0 + ako);
            cpa16(sAl + ab + arow * ASTR + ako, Al + arow * aStr + k0 + ako);
#pragma unroll
            for (int i = 0; i < 4; i++) {
                int c = tid + (i << 8);
                int br = c >> 3, bko = (c & 7) << 3;
                int g = growf(br, j0);
                cpa16(sBh + bb + br * ASTR + bko, Bh + g * bStr + k0 + bko);
                cpa16(sBl + bb + br * ASTR + bko, Bl + g * bStr + k0 + bko);
            }
            cpcommit();
            cpwait1();
        } else {
            cpwait0();
        }
        __syncthreads();

        const __half* Abh = sAh + (s & 1) * 2304;
        const __half* Abl = sAl + (s & 1) * 2304;
        const __half* Bbh = sBh + (s & 1) * 9216;
        const __half* Bbl = sBl + (s & 1) * 9216;
#pragma unroll
        for (int kk = 0; kk < 64; kk += 16) {
            unsigned ah0[4], ah1[4], al0[4], al1[4];
            const int aoff = (lane & 15) * ASTR + kk + ((lane >> 4) << 3);
            ldmA4(ah0, sptr(Abh + aoff));
            ldmA4(ah1, sptr(Abh + 16 * ASTR + aoff));
            ldmA4(al0, sptr(Abl + aoff));
            ldmA4(al1, sptr(Abl + 16 * ASTR + aoff));
#pragma unroll
            for (int nf = 0; nf < 2; nf++) {
                unsigned bh[2], bl[2];
                const int boff = ((w << 4) + (nf << 3) + (lane & 7)) * ASTR +
                                 kk + (((lane >> 3) & 1) << 3);
                ldmB2(bh, sptr(Bbh + boff));
                ldmB2(bl, sptr(Bbl + boff));
                mma16816(acc[0][nf], ah0, bh);
                mma16816(acc[1][nf], ah1, bh);
                mma16816(acc[0][nf], ah0, bl);
                mma16816(acc[1][nf], ah1, bl);
                mma16816(acc[0][nf], al0, bh);
                mma16816(acc[1][nf], al1, bh);
            }
        }
        __syncthreads();
    }
}

// ---------------- decoder core: out[b][toff+o] = h2[b,:] . Wdec[o,:] + bdec[o] ----------------
// smf: sh2[32][257] fp32, then sWd[4][257]
__device__ void dec_core(float* smf, int db, int tid,
                         const float* __restrict__ h2, const float* __restrict__ wdec,
                         const float* __restrict__ bdec, float* __restrict__ outp, int toff)
{
    float* sh2 = smf;
    float* sWd = smf + 32 * 257;
    const int o0 = db * 4;
    const int oo = tid & 3, b = tid >> 2;
    float acc = 0.0f;
    for (int k0 = 0; k0 < HID; k0 += 256) {
        __syncthreads();
        for (int li = tid; li < 8192; li += 256) {
            int r = li >> 8, c = li & 255;
            sh2[r * 257 + c] = h2[r * HID + k0 + c];
        }
        for (int li = tid; li < 1024; li += 256) {
            int r = li >> 8, c = li & 255;
            sWd[r * 257 + c] = wdec[(o0 + r) * HID + k0 + c];
        }
        __syncthreads();
        if (tid < 128) {
#pragma unroll 8
            for (int k = 0; k < 256; k++)
                acc += sh2[b * 257 + k] * sWd[oo * 257 + k];
        }
    }
    if (tid < 128)
        outp[b * OUTW + toff + o0 + oo] = acc + bdec[o0 + oo];
}

// ---------------- prep 1: splits, padding, frames, biases, zeroing ----------------
__global__ void k_prep1(
    const float* __restrict__ wih1, const float* __restrict__ whh1,
    const float* __restrict__ wih2, const float* __restrict__ whh2,
    const float* __restrict__ wih3, const float* __restrict__ whh3,
    const float* __restrict__ seq,
    const float* __restrict__ bi1, const float* __restrict__ bh1,
    const float* __restrict__ bi2, const float* __restrict__ bh2,
    const float* __restrict__ bi3, const float* __restrict__ bh3)
{
    const long i0 = (long)blockIdx.x * blockDim.x + threadIdx.x;
    const long stride = (long)gridDim.x * blockDim.x;

    // 5 recurrent/inter-layer weight matrices -> hi/lo fp16
    for (long i = i0; i < 5L * G4 * HID; i += stride) {
        int m = (int)(i >> 22);
        long off = i & 4194303L;
        const float* p = (m == 0) ? whh1 : (m == 1) ? wih2 : (m == 2) ? whh2
                                 : (m == 3) ? wih3 : whh3;
        float v = p[off];
        __half hi = __float2half_rn(v);
        (&g_Wh[0][0][0])[i] = hi;
        (&g_Wl[0][0][0])[i] = __float2half_rn(v - __half2float(hi));
    }
    // W_ih1 padded 132 -> 192
    for (long i = i0; i < (long)G4 * KP; i += stride) {
        int r = (int)(i / KP), k = (int)(i % KP);
        float v = (k < IND) ? wih1[r * IND + k] : 0.0f;
        __half hi = __float2half_rn(v);
        (&g_W1h[0][0])[i] = hi;
        (&g_W1l[0][0])[i] = __float2half_rn(v - __half2float(hi));
    }
    // frames: seq[b][t][k] -> g_x[t][b][k] padded
    for (long i = i0; i < (long)NT * NB * KP; i += stride) {
        int t = (int)(i / (NB * KP));
        int rem = (int)(i % (NB * KP));
        int b = rem / KP, k = rem % KP;
        float v = (k < IND) ? seq[((long)b * NT + t) * IND + k] : 0.0f;
        __half hi = __float2half_rn(v);
        (&g_xh[0][0][0])[i] = hi;
        (&g_xl[0][0][0])[i] = __float2half_rn(v - __half2float(hi));
    }
    // bias sums
    for (long i = i0; i < 3L * G4; i += stride) {
        int l = (int)(i >> 12), r = (int)(i & 4095);
        const float* pi = (l == 0) ? bi1 : (l == 1) ? bi2 : bi3;
        const float* ph = (l == 0) ? bh1 : (l == 1) ? bh2 : bh3;
        g_bs[l][r] = pi[r] + ph[r];
    }
    // zero state (fresh every replay -> deterministic)
    for (long i = i0; i < 3L * NB * HID; i += stride) (&g_c[0][0][0])[i] = 0.0f;
    for (long i = i0; i < 2L * 3 * NB * HID; i += stride) {
        (&g_hf[0][0][0][0])[i] = 0.0f;
        (&g_hh[0][0][0][0])[i] = __float2half_rn(0.0f);
        (&g_hl[0][0][0][0])[i] = __float2half_rn(0.0f);
    }
}

// ---------------- prep 2: Mw = W_ih1 @ W_dec (fp32, then split) + bsM ----------------
// dyn smem: sW1[128][133] fp32, sWd[132][64] fp32
__global__ void k_mw(const float* __restrict__ wih1, const float* __restrict__ wdec,
                     const float* __restrict__ bdec)
{
    extern __shared__ __align__(16) char smraw[];
    const int tid = threadIdx.x, bid = blockIdx.x;

    if (bid >= 512) {  // bsM: 16 blocks x 256 threads = 4096 rows
        int r = (bid - 512) * 256 + tid;
        float a = 0.0f;
        for (int j = 0; j < IND; j++) a += wih1[r * IND + j] * bdec[j];
        g_bsM[r] = g_bs[0][r] + a;
        return;
    }
    float* sW1 = (float*)smraw;              // [128][133]
    float* sWd = (float*)smraw + 128 * 133;  // [132][64]
    const int r0 = (bid >> 4) * 128;
    const int c0 = (bid & 15) * 64;

    for (int li = tid; li < 128 * IND; li += 256) {
        int rr = li / IND, jj = li % IND;
        sW1[rr * 133 + jj] = wih1[(r0 + rr) * IND + jj];
    }
    for (int li = tid; li < IND * 64; li += 256) {
        int j = li >> 6, cc = li & 63;
        sWd[j * 64 + cc] = wdec[j * HID + c0 + cc];
    }
    __syncthreads();

    const int ty = tid >> 4, tx = tid & 15;
    float a[8][4];
#pragma unroll
    for (int i = 0; i < 8; i++)
#pragma unroll
        for (int q = 0; q < 4; q++) a[i][q] = 0.0f;

    for (int j = 0; j < IND; j++) {
        float4 wd = *(const float4*)&sWd[j * 64 + tx * 4];
#pragma unroll
        for (int i = 0; i < 8; i++) {
            float w1 = sW1[(ty + 16 * i) * 133 + j];
            a[i][0] += w1 * wd.x; a[i][1] += w1 * wd.y;
            a[i][2] += w1 * wd.z; a[i][3] += w1 * wd.w;
        }
    }
#pragma unroll
    for (int i = 0; i < 8; i++)
#pragma unroll
        for (int q = 0; q < 4; q++) {
            int r = r0 + ty + 16 * i, c = c0 + tx * 4 + q;
            float v = a[i][q];
            __half hi = __float2half_rn(v);
            g_Mwh[r][c] = hi;
            g_Mwl[r][c] = __float2half_rn(v - __half2float(hi));
        }
}

// ---------------- the per-timestep kernel ----------------
// blocks 0..95: gates (layer = bid/32, 32 hidden units x 4 gates per block)
// blocks 96..128: decoder for step t-1 (t>0)
__global__ void k_step(int t, int gt, const float* __restrict__ wdec,
                       const float* __restrict__ bdec, float* __restrict__ dout)
{
    extern __shared__ __align__(16) char smraw[];
    __half* sm = (__half*)smraw;
    const int tid = threadIdx.x, bid = blockIdx.x;
    const int prev = (t & 1) ^ 1, cur = t & 1;

    if (bid >= 96) {
        if (t > 0)
            dec_core((float*)smraw, bid - 96, tid, &g_hf[prev][2][0][0],
                     wdec, bdec, dout, (t - 1) * IND);
        return;
    }

    const int l = bid >> 5, j0 = (bid & 31) << 5;
    float acc[2][2][4];
#pragma unroll
    for (int a = 0; a < 2; a++)
#pragma unroll
        for (int b = 0; b < 2; b++)
#pragma unroll
            for (int c = 0; c < 4; c++) acc[a][b][c] = 0.0f;

    const __half *Ah1, *Al1, *Bh1, *Bl1, *Ah2, *Al2, *Bh2, *Bl2;
    int aStr1, bStr1, K1;
    if (l == 0) {
        if (gt) {
            Ah1 = &g_xh[t][0][0]; Al1 = &g_xl[t][0][0]; aStr1 = KP; K1 = KP;
            Bh1 = &g_W1h[0][0];   Bl1 = &g_W1l[0][0];   bStr1 = KP;
        } else {
            Ah1 = &g_hh[prev][2][0][0]; Al1 = &g_hl[prev][2][0][0]; aStr1 = HID; K1 = HID;
            Bh1 = &g_Mwh[0][0];         Bl1 = &g_Mwl[0][0];         bStr1 = HID;
        }
        Ah2 = &g_hh[prev][0][0][0]; Al2 = &g_hl[prev][0][0][0];
        Bh2 = &g_Wh[0][0][0];       Bl2 = &g_Wl[0][0][0];
    } else if (l == 1) {
        Ah1 = &g_hh[prev][0][0][0]; Al1 = &g_hl[prev][0][0][0]; aStr1 = HID; K1 = HID;
        Bh1 = &g_Wh[1][0][0];       Bl1 = &g_Wl[1][0][0];       bStr1 = HID;
        Ah2 = &g_hh[prev][1][0][0]; Al2 = &g_hl[prev][1][0][0];
        Bh2 = &g_Wh[2][0][0];       Bl2 = &g_Wl[2][0][0];
    } else {
        Ah1 = &g_hh[prev][1][0][0]; Al1 = &g_hl[prev][1][0][0]; aStr1 = HID; K1 = HID;
        Bh1 = &g_Wh[3][0][0];       Bl1 = &g_Wl[3][0][0];       bStr1 = HID;
        Ah2 = &g_hh[prev][2][0][0]; Al2 = &g_hl[prev][2][0][0];
        Bh2 = &g_Wh[4][0][0];       Bl2 = &g_Wl[4][0][0];
    }

    gemm2(acc, sm, Ah1, Al1, aStr1, Bh1, Bl1, bStr1, j0, K1, tid);
    gemm2(acc, sm, Ah2, Al2, HID, Bh2, Bl2, HID, j0, HID, tid);

    // stage gates + bias to smem (overlaps dead A region)
    float* G = (float*)smraw;  // [32][129]
    const int lane = tid & 31, w = tid >> 5;
#pragma unroll
    for (int mi = 0; mi < 2; mi++)
#pragma unroll
        for (int nf = 0; nf < 2; nf++)
#pragma unroll
            for (int r = 0; r < 4; r++) {
                int m = mi * 16 + (lane >> 2) + ((r >> 1) << 3);
                int n = (w << 4) + (nf << 3) + ((lane & 3) << 1) + (r & 1);
                int row = growf(n, j0);
                float bias = (l == 0 && !gt) ? g_bsM[row] : g_bs[l][row];
                G[m * 129 + n] = acc[mi][nf][r] + bias;
            }
    __syncthreads();

    // pointwise LSTM update
    const int b = tid >> 3;
    const int jj0 = (tid & 7) << 2;
#pragma unroll
    for (int q = 0; q < 4; q++) {
        const int jj = jj0 + q, j = j0 + jj;
        float gi = G[b * 129 + jj];
        float gf = G[b * 129 + 32 + jj];
        float gg = G[b * 129 + 64 + jj];
        float go = G[b * 129 + 96 + jj];
        float c0 = g_c[l][b][j];
        float cn = sigm(gf) * c0 + sigm(gi) * tanhf(gg);
        float hn = sigm(go) * tanhf(cn);
        g_c[l][b][j] = cn;
        g_hf[cur][l][b][j] = hn;
        __half hh2 = __float2half_rn(hn);
        g_hh[cur][l][b][j] = hh2;
        g_hl[cur][l][b][j] = __float2half_rn(hn - __half2float(hh2));
    }
}

// ---------------- final decoder (out[99]) ----------------
__global__ void k_dec_final(const float* __restrict__ wdec, const float* __restrict__ bdec,
                            float* __restrict__ dout)
{
    __shared__ float smf[32 * 257 + 4 * 257];
    // step 99 wrote cur = 99&1 = 1
    dec_core(smf, blockIdx.x, threadIdx.x, &g_hf[1][2][0][0], wdec, bdec, dout, 99 * IND);
}

// ---------------- host ----------------
#define STEP_SMEM 92160   // halves: sAh 4608 + sAl 4608 + sBh 18432 + sBl 18432 -> *2 bytes
#define MW_SMEM   101888  // (128*133 + 132*64) * 4

extern "C" void kernel_launch(void* const* d_in, const int* in_sizes, int n_in,
                              void* d_out, int out_size) {
    (void)in_sizes; (void)n_in; (void)out_size;
    const float* seq  = (const float*)d_in[0];
    const float* Wih1 = (const float*)d_in[1];
    const float* Whh1 = (const float*)d_in[2];
    const float* bih1 = (const float*)d_in[3];
    const float* bhh1 = (const float*)d_in[4];
    const float* Wih2 = (const float*)d_in[5];
    const float* Whh2 = (const float*)d_in[6];
    const float* bih2 = (const float*)d_in[7];
    const float* bhh2 = (const float*)d_in[8];
    const float* Wih3 = (const float*)d_in[9];
    const float* Whh3 = (const float*)d_in[10];
    const float* bih3 = (const float*)d_in[11];
    const float* bhh3 = (const float*)d_in[12];
    const float* Wdec = (const float*)d_in[13];
    const float* bdec = (const float*)d_in[14];
    float* out = (float*)d_out;

    // attribute set is idempotent; safe during capture (not a stream op)
    cudaFuncSetAttribute(k_step, cudaFuncAttributeMaxDynamicSharedMemorySize, STEP_SMEM);
    cudaFuncSetAttribute(k_mw, cudaFuncAttributeMaxDynamicSharedMemorySize, MW_SMEM);

    k_prep1<<<2048, 256>>>(Wih1, Whh1, Wih2, Whh2, Wih3, Whh3, seq,
                           bih1, bhh1, bih2, bhh2, bih3, bhh3);
    k_mw<<<528, 256, MW_SMEM>>>(Wih1, Wdec, bdec);
    for (int t = 0; t < NT; t++) {
        int gt = (t % 10) < 5;
        k_step<<<129, 256, STEP_SMEM>>>(t, gt, Wdec, bdec, out);
    }
    k_dec_final<<<33, 256>>>(Wdec, bdec, out);
}

// round 6
// speedup vs baseline: 1.0469x; 1.0469x over previous
#include <cuda_runtime.h>
#include <cuda_fp16.h>
#include <cuda_fp8.h>
#include <math.h>

#define HID   1024
#define G4    4096
#define NB    32
#define NT    100
#define IND   132
#define KP    192
#define OUTW  13200   // 100*132
#define ASTR  72      // smem fp16 row stride in halves (64+8 pad)
#define DEPTH 5
#define LO_SCALE 16384.0f
#define LO_INV   (1.0f/16384.0f)

// smem byte offsets for the 5-slot ring
#define SM_AH 0          // 5 * 4608  (A hi fp16, 32x72 halves)
#define SM_AL 23040      // 5 * 4608  (A lo fp16)
#define SM_BH 46080      // 5 * 18432 (B hi fp16, 128x72 halves)
#define SM_B8 138240     // 5 * 10240 (B lo fp8, 128x80 bytes)
#define STEP_SMEM 189440

// ---------------- persistent device scratch ----------------
__device__ __half         g_Wh[5][G4][HID];   // hi: W_hh1, W_ih2, W_hh2, W_ih3, W_hh3
__device__ unsigned char  g_Wl8[5][G4][HID];  // lo residual, e4m3, scaled by 2^14
__device__ __half         g_Mwh[G4][HID];     // Mw = W_ih1 @ W_dec
__device__ unsigned char  g_Mwl8[G4][HID];
__device__ __half         g_W1h[G4][KP];      // W_ih1 padded 132->192
__device__ unsigned char  g_W1l8[G4][KP];
__device__ __half         g_xh[NT][NB][KP];   // frames padded, hi/lo fp16
__device__ __half         g_xl[NT][NB][KP];
__device__ float          g_hf[2][3][NB][HID];
__device__ __half         g_hh[2][3][NB][HID];
__device__ __half         g_hl[2][3][NB][HID];
__device__ float          g_c[3][NB][HID];
__device__ float          g_bs[3][G4];        // b_ih + b_hh
__device__ float          g_bsM[G4];          // g_bs[0] + W_ih1@b_dec

// ---------------- asm helpers ----------------
__device__ __forceinline__ unsigned sptr(const void* p) {
    return (unsigned)__cvta_generic_to_shared(p);
}
__device__ __forceinline__ void cpa16(void* s, const void* g) {
    asm volatile("cp.async.cg.shared.global [%0], [%1], 16;" :: "r"(sptr(s)), "l"(g));
}
__device__ __forceinline__ void cpcommit() { asm volatile("cp.async.commit_group;"); }
__device__ __forceinline__ void cpwait3()  { asm volatile("cp.async.wait_group 3;"); }

__device__ __forceinline__ void ldmA4(unsigned a[4], unsigned addr) {
    asm volatile("ldmatrix.sync.aligned.m8n8.x4.shared.b16 {%0,%1,%2,%3}, [%4];"
                 : "=r"(a[0]), "=r"(a[1]), "=r"(a[2]), "=r"(a[3]) : "r"(addr));
}
__device__ __forceinline__ void ldmB2(unsigned b[2], unsigned addr) {
    asm volatile("ldmatrix.sync.aligned.m8n8.x2.shared.b16 {%0,%1}, [%2];"
                 : "=r"(b[0]), "=r"(b[1]) : "r"(addr));
}
__device__ __forceinline__ void mma16816(float c[4], const unsigned a[4], const unsigned b[2]) {
    asm volatile("mma.sync.aligned.m16n8k16.row.col.f32.f16.f16.f32 "
                 "{%0,%1,%2,%3}, {%4,%5,%6,%7}, {%8,%9}, {%0,%1,%2,%3};"
                 : "+f"(c[0]), "+f"(c[1]), "+f"(c[2]), "+f"(c[3])
                 : "r"(a[0]), "r"(a[1]), "r"(a[2]), "r"(a[3]), "r"(b[0]), "r"(b[1]));
}
__device__ __forceinline__ unsigned cvt8x2(unsigned short v) {
    unsigned r;
    asm("cvt.rn.f16x2.e4m3x2 %0, %1;" : "=r"(r) : "h"(v));
    return r;
}
__device__ __forceinline__ float sigm(float x) { return 1.0f / (1.0f + __expf(-x)); }
__device__ __forceinline__ int growf(int n, int j0) { return ((n >> 5) << 10) + j0 + (n & 31); }

// ---------------- decoder core ----------------
// smf: sh2[32][257] fp32, then sWd[4][257]
__device__ void dec_core(float* smf, int db, int tid,
                         const float* __restrict__ h2, const float* __restrict__ wdec,
                         const float* __restrict__ bdec, float* __restrict__ outp, int toff)
{
    float* sh2 = smf;
    float* sWd = smf + 32 * 257;
    const int o0 = db * 4;
    const int oo = tid & 3, b = (tid >> 2) & 31;
    float acc = 0.0f;
    for (int k0 = 0; k0 < HID; k0 += 256) {
        __syncthreads();
        for (int li = tid; li < 8192; li += 256) {
            int r = li >> 8, c = li & 255;
            sh2[r * 257 + c] = h2[r * HID + k0 + c];
        }
        for (int li = tid; li < 1024; li += 256) {
            int r = li >> 8, c = li & 255;
            sWd[r * 257 + c] = wdec[(o0 + r) * HID + k0 + c];
        }
        __syncthreads();
        if (tid < 128) {
#pragma unroll 8
            for (int k = 0; k < 256; k++)
                acc += sh2[b * 257 + k] * sWd[oo * 257 + k];
        }
    }
    if (tid < 128)
        outp[b * OUTW + toff + o0 + oo] = acc + bdec[o0 + oo];
}

// ---------------- prep 1 ----------------
__global__ void k_prep1(
    const float* __restrict__ wih1, const float* __restrict__ whh1,
    const float* __restrict__ wih2, const float* __restrict__ whh2,
    const float* __restrict__ wih3, const float* __restrict__ whh3,
    const float* __restrict__ seq,
    const float* __restrict__ bi1, const float* __restrict__ bh1,
    const float* __restrict__ bi2, const float* __restrict__ bh2,
    const float* __restrict__ bi3, const float* __restrict__ bh3)
{
    const long i0 = (long)blockIdx.x * blockDim.x + threadIdx.x;
    const long stride = (long)gridDim.x * blockDim.x;

    // 5 recurrent/inter-layer weight matrices -> fp16 hi + fp8 lo
    for (long i = i0; i < 5L * G4 * HID; i += stride) {
        int m = (int)(i >> 22);
        long off = i & 4194303L;
        const float* p = (m == 0) ? whh1 : (m == 1) ? wih2 : (m == 2) ? whh2
                                 : (m == 3) ? wih3 : whh3;
        float v = p[off];
        __half hi = __float2half_rn(v);
        float lo = v - __half2float(hi);
        (&g_Wh[0][0][0])[i]  = hi;
        (&g_Wl8[0][0][0])[i] = __nv_cvt_float_to_fp8(lo * LO_SCALE, __NV_SATFINITE, __NV_E4M3);
    }
    // W_ih1 padded 132 -> 192
    for (long i = i0; i < (long)G4 * KP; i += stride) {
        int r = (int)(i / KP), k = (int)(i % KP);
        float v = (k < IND) ? wih1[r * IND + k] : 0.0f;
        __half hi = __float2half_rn(v);
        float lo = v - __half2float(hi);
        (&g_W1h[0][0])[i]  = hi;
        (&g_W1l8[0][0])[i] = __nv_cvt_float_to_fp8(lo * LO_SCALE, __NV_SATFINITE, __NV_E4M3);
    }
    // frames: seq[b][t][k] -> g_x[t][b][k] padded, hi/lo fp16
    for (long i = i0; i < (long)NT * NB * KP; i += stride) {
        int t = (int)(i / (NB * KP));
        int rem = (int)(i % (NB * KP));
        int b = rem / KP, k = rem % KP;
        float v = (k < IND) ? seq[((long)b * NT + t) * IND + k] : 0.0f;
        __half hi = __float2half_rn(v);
        (&g_xh[0][0][0])[i] = hi;
        (&g_xl[0][0][0])[i] = __float2half_rn(v - __half2float(hi));
    }
    // bias sums
    for (long i = i0; i < 3L * G4; i += stride) {
        int l = (int)(i >> 12), r = (int)(i & 4095);
        const float* pi = (l == 0) ? bi1 : (l == 1) ? bi2 : bi3;
        const float* ph = (l == 0) ? bh1 : (l == 1) ? bh2 : bh3;
        g_bs[l][r] = pi[r] + ph[r];
    }
    // zero state (fresh every replay -> deterministic)
    for (long i = i0; i < 3L * NB * HID; i += stride) (&g_c[0][0][0])[i] = 0.0f;
    for (long i = i0; i < 2L * 3 * NB * HID; i += stride) {
        (&g_hf[0][0][0][0])[i] = 0.0f;
        (&g_hh[0][0][0][0])[i] = __float2half_rn(0.0f);
        (&g_hl[0][0][0][0])[i] = __float2half_rn(0.0f);
    }
}

// ---------------- prep 2: Mw = W_ih1 @ W_dec + bsM ----------------
__global__ void k_mw(const float* __restrict__ wih1, const float* __restrict__ wdec,
                     const float* __restrict__ bdec)
{
    extern __shared__ __align__(16) char smraw[];
    const int tid = threadIdx.x, bid = blockIdx.x;

    if (bid >= 512) {  // bsM: 16 blocks x 256 threads = 4096 rows
        int r = (bid - 512) * 256 + tid;
        float a = 0.0f;
        for (int j = 0; j < IND; j++) a += wih1[r * IND + j] * bdec[j];
        g_bsM[r] = g_bs[0][r] + a;
        return;
    }
    float* sW1 = (float*)smraw;              // [128][133]
    float* sWd = (float*)smraw + 128 * 133;  // [132][64]
    const int r0 = (bid >> 4) * 128;
    const int c0 = (bid & 15) * 64;

    for (int li = tid; li < 128 * IND; li += 256) {
        int rr = li / IND, jj = li % IND;
        sW1[rr * 133 + jj] = wih1[(r0 + rr) * IND + jj];
    }
    for (int li = tid; li < IND * 64; li += 256) {
        int j = li >> 6, cc = li & 63;
        sWd[j * 64 + cc] = wdec[j * HID + c0 + cc];
    }
    __syncthreads();

    const int ty = tid >> 4, tx = tid & 15;
    float a[8][4];
#pragma unroll
    for (int i = 0; i < 8; i++)
#pragma unroll
        for (int q = 0; q < 4; q++) a[i][q] = 0.0f;

    for (int j = 0; j < IND; j++) {
        float4 wd = *(const float4*)&sWd[j * 64 + tx * 4];
#pragma unroll
        for (int i = 0; i < 8; i++) {
            float w1 = sW1[(ty + 16 * i) * 133 + j];
            a[i][0] += w1 * wd.x; a[i][1] += w1 * wd.y;
            a[i][2] += w1 * wd.z; a[i][3] += w1 * wd.w;
        }
    }
#pragma unroll
    for (int i = 0; i < 8; i++)
#pragma unroll
        for (int q = 0; q < 4; q++) {
            int r = r0 + ty + 16 * i, c = c0 + tx * 4 + q;
            float v = a[i][q];
            __half hi = __float2half_rn(v);
            float lo = v - __half2float(hi);
            g_Mwh[r][c] = hi;
            g_Mwl8[r][c] = __nv_cvt_float_to_fp8(lo * LO_SCALE, __NV_SATFINITE, __NV_E4M3);
        }
}

// ---------------- the per-timestep kernel ----------------
// blocks 0..95: gates (layer = bid/32, 32 hidden units x 4 gates per block)
// blocks 96..128: decoder for step t-1 (t>0)
__global__ void k_step(int t, int gt, const float* __restrict__ wdec,
                       const float* __restrict__ bdec, float* __restrict__ dout)
{
    extern __shared__ __align__(16) char smraw[];
    const int tid = threadIdx.x, bid = blockIdx.x;
    const int prev = (t & 1) ^ 1, cur = t & 1;

    if (bid >= 96) {
        if (t > 0)
            dec_core((float*)smraw, bid - 96, tid, &g_hf[prev][2][0][0],
                     wdec, bdec, dout, (t - 1) * IND);
        return;
    }

    const int l = bid >> 5, j0 = (bid & 31) << 5;
    const int lane = tid & 31, w = tid >> 5;

    // segment descriptors: [seg] x {A-hi, A-lo fp16, B-hi fp16, B-lo fp8}
    const __half *Ah[2], *Al[2], *Bh[2];
    const unsigned char* B8[2];
    int aStr[2], bStr[2], nst1;

    if (l == 0) {
        if (gt) {
            Ah[0] = &g_xh[t][0][0]; Al[0] = &g_xl[t][0][0]; aStr[0] = KP;
            Bh[0] = &g_W1h[0][0];   B8[0] = &g_W1l8[0][0];  bStr[0] = KP;
            nst1 = KP >> 6;   // 3
        } else {
            Ah[0] = &g_hh[prev][2][0][0]; Al[0] = &g_hl[prev][2][0][0]; aStr[0] = HID;
            Bh[0] = &g_Mwh[0][0];         B8[0] = &g_Mwl8[0][0];        bStr[0] = HID;
            nst1 = 16;
        }
        Ah[1] = &g_hh[prev][0][0][0]; Al[1] = &g_hl[prev][0][0][0];
        Bh[1] = &g_Wh[0][0][0];       B8[1] = &g_Wl8[0][0][0];
    } else if (l == 1) {
        Ah[0] = &g_hh[prev][0][0][0]; Al[0] = &g_hl[prev][0][0][0]; aStr[0] = HID;
        Bh[0] = &g_Wh[1][0][0];       B8[0] = &g_Wl8[1][0][0];      bStr[0] = HID;
        nst1 = 16;
        Ah[1] = &g_hh[prev][1][0][0]; Al[1] = &g_hl[prev][1][0][0];
        Bh[1] = &g_Wh[2][0][0];       B8[1] = &g_Wl8[2][0][0];
    } else {
        Ah[0] = &g_hh[prev][1][0][0]; Al[0] = &g_hl[prev][1][0][0]; aStr[0] = HID;
        Bh[0] = &g_Wh[3][0][0];       B8[0] = &g_Wl8[3][0][0];      bStr[0] = HID;
        nst1 = 16;
        Ah[1] = &g_hh[prev][2][0][0]; Al[1] = &g_hl[prev][2][0][0];
    }
    if (l != 0) { aStr[1] = HID; bStr[1] = HID; }
    else        { aStr[1] = HID; bStr[1] = HID; }
    if (l == 2) { Bh[1] = &g_Wh[4][0][0]; B8[1] = &g_Wl8[4][0][0]; }
    const int nstTot = nst1 + 16;

    // per-thread copy geometry (stage-invariant)
    const int aRow = tid >> 3, aKo = (tid & 7) << 3;                  // A: 1 chunk
    int bRow[4], bKo[4], bG[4];                                      // B-hi: 4 chunks
#pragma unroll
    for (int i = 0; i < 4; i++) {
        int c = tid + (i << 8);
        bRow[i] = c >> 3; bKo[i] = (c & 7) << 3;
        bG[i] = growf(bRow[i], j0);
    }
    int b8Row[2], b8Ch[2], b8G[2];                                   // B-lo8: 2 chunks
#pragma unroll
    for (int i = 0; i < 2; i++) {
        int c = tid + (i << 8);
        b8Row[i] = c >> 2; b8Ch[i] = (c & 3) << 4;
        b8G[i] = growf(b8Row[i], j0);
    }

    auto issue = [&](int s) {
        const int seg = (s >= nst1) ? 1 : 0;
        const int k0 = (s - (seg ? nst1 : 0)) << 6;
        const int slot = s % DEPTH;
        __half* dAh = (__half*)(smraw + SM_AH) + slot * 2304 + aRow * ASTR + aKo;
        __half* dAl = (__half*)(smraw + SM_AL) + slot * 2304 + aRow * ASTR + aKo;
        cpa16(dAh, Ah[seg] + aRow * aStr[seg] + k0 + aKo);
        cpa16(dAl, Al[seg] + aRow * aStr[seg] + k0 + aKo);
        __half* dBh = (__half*)(smraw + SM_BH) + slot * 9216;
#pragma unroll
        for (int i = 0; i < 4; i++)
            cpa16(dBh + bRow[i] * ASTR + bKo[i],
                  Bh[seg] + (size_t)bG[i] * bStr[seg] + k0 + bKo[i]);
        unsigned char* dB8 = (unsigned char*)(smraw + SM_B8) + slot * 10240;
#pragma unroll
        for (int i = 0; i < 2; i++)
            cpa16(dB8 + b8Row[i] * 80 + b8Ch[i],
                  B8[seg] + (size_t)b8G[i] * bStr[seg] + k0 + b8Ch[i]);
    };

    float accH[2][2][4], accL[2][2][4];
#pragma unroll
    for (int a = 0; a < 2; a++)
#pragma unroll
        for (int b = 0; b < 2; b++)
#pragma unroll
            for (int c = 0; c < 4; c++) { accH[a][b][c] = 0.0f; accL[a][b][c] = 0.0f; }

    // prologue: fill DEPTH-1 slots
#pragma unroll
    for (int s = 0; s < DEPTH - 1; s++) { issue(s); cpcommit(); }

    for (int s = 0; s < nstTot; s++) {
        cpwait3();
        __syncthreads();
        const int slot = s % DEPTH;
        const __half* Abh = (const __half*)(smraw + SM_AH) + slot * 2304;
        const __half* Abl = (const __half*)(smraw + SM_AL) + slot * 2304;
        const __half* Bbh = (const __half*)(smraw + SM_BH) + slot * 9216;
        const unsigned char* Bb8 = (const unsigned char*)(smraw + SM_B8) + slot * 10240;

#pragma unroll
        for (int kk = 0; kk < 64; kk += 16) {
            unsigned ah0[4], ah1[4], al0[4], al1[4];
            const int aoff = (lane & 15) * ASTR + kk + ((lane >> 4) << 3);
            ldmA4(ah0, sptr(Abh + aoff));
            ldmA4(ah1, sptr(Abh + 16 * ASTR + aoff));
            ldmA4(al0, sptr(Abl + aoff));
            ldmA4(al1, sptr(Abl + 16 * ASTR + aoff));
#pragma unroll
            for (int nf = 0; nf < 2; nf++) {
                unsigned bh[2];
                const int boff = ((w << 4) + (nf << 3) + (lane & 7)) * ASTR +
                                 kk + (((lane >> 3) & 1) << 3);
                ldmB2(bh, sptr(Bbh + boff));
                // fp8 lo fragment (ldmatrix-equivalent layout)
                const unsigned char* p8 = Bb8 + ((w << 4) + (nf << 3) + (lane >> 2)) * 80 +
                                          kk + ((lane & 3) << 1);
                unsigned bl[2];
                bl[0] = cvt8x2(*(const unsigned short*)p8);
                bl[1] = cvt8x2(*(const unsigned short*)(p8 + 8));
                mma16816(accH[0][nf], ah0, bh);
                mma16816(accH[1][nf], ah1, bh);
                mma16816(accH[0][nf], al0, bh);
                mma16816(accH[1][nf], al1, bh);
                mma16816(accL[0][nf], ah0, bl);
                mma16816(accL[1][nf], ah1, bl);
            }
        }
        if (s + DEPTH - 1 < nstTot) issue(s + DEPTH - 1);
        cpcommit();   // unconditional: keeps wait_group 3 uniformly correct
    }
    __syncthreads();  // all warps done with smem before G staging reuses it

    // stage gates + bias to smem
    float* G = (float*)smraw;  // [32][129]
#pragma unroll
    for (int mi = 0; mi < 2; mi++)
#pragma unroll
        for (int nf = 0; nf < 2; nf++)
#pragma unroll
            for (int r = 0; r < 4; r++) {
                int m = mi * 16 + (lane >> 2) + ((r >> 1) << 3);
                int n = (w << 4) + (nf << 3) + ((lane & 3) << 1) + (r & 1);
                int row = growf(n, j0);
                float bias = (l == 0 && !gt) ? g_bsM[row] : g_bs[l][row];
                G[m * 129 + n] = accH[mi][nf][r] + accL[mi][nf][r] * LO_INV + bias;
            }
    __syncthreads();

    // pointwise LSTM update
    const int b = tid >> 3;
    const int jj0 = (tid & 7) << 2;
#pragma unroll
    for (int q = 0; q < 4; q++) {
        const int jj = jj0 + q, j = j0 + jj;
        float gi = G[b * 129 + jj];
        float gf = G[b * 129 + 32 + jj];
        float gg = G[b * 129 + 64 + jj];
        float go = G[b * 129 + 96 + jj];
        float c0 = g_c[l][b][j];
        float cn = sigm(gf) * c0 + sigm(gi) * tanhf(gg);
        float hn = sigm(go) * tanhf(cn);
        g_c[l][b][j] = cn;
        g_hf[cur][l][b][j] = hn;
        __half hh2 = __float2half_rn(hn);
        g_hh[cur][l][b][j] = hh2;
        g_hl[cur][l][b][j] = __float2half_rn(hn - __half2float(hh2));
    }
}

// ---------------- final decoder (out[99]) ----------------
__global__ void k_dec_final(const float* __restrict__ wdec, const float* __restrict__ bdec,
                            float* __restrict__ dout)
{
    __shared__ float smf[32 * 257 + 4 * 257];
    dec_core(smf, blockIdx.x, threadIdx.x, &g_hf[1][2][0][0], wdec, bdec, dout, 99 * IND);
}

// ---------------- host ----------------
#define MW_SMEM 101888  // (128*133 + 132*64) * 4

extern "C" void kernel_launch(void* const* d_in, const int* in_sizes, int n_in,
                              void* d_out, int out_size) {
    (void)in_sizes; (void)n_in; (void)out_size;
    const float* seq  = (const float*)d_in[0];
    const float* Wih1 = (const float*)d_in[1];
    const float* Whh1 = (const float*)d_in[2];
    const float* bih1 = (const float*)d_in[3];
    const float* bhh1 = (const float*)d_in[4];
    const float* Wih2 = (const float*)d_in[5];
    const float* Whh2 = (const float*)d_in[6];
    const float* bih2 = (const float*)d_in[7];
    const float* bhh2 = (const float*)d_in[8];
    const float* Wih3 = (const float*)d_in[9];
    const float* Whh3 = (const float*)d_in[10];
    const float* bih3 = (const float*)d_in[11];
    const float* bhh3 = (const float*)d_in[12];
    const float* Wdec = (const float*)d_in[13];
    const float* bdec = (const float*)d_in[14];
    float* out = (float*)d_out;

    cudaFuncSetAttribute(k_step, cudaFuncAttributeMaxDynamicSharedMemorySize, STEP_SMEM);
    cudaFuncSetAttribute(k_mw, cudaFuncAttributeMaxDynamicSharedMemorySize, MW_SMEM);

    k_prep1<<<2048, 256>>>(Wih1, Whh1, Wih2, Whh2, Wih3, Whh3, seq,
                           bih1, bhh1, bih2, bhh2, bih3, bhh3);
    k_mw<<<528, 256, MW_SMEM>>>(Wih1, Wdec, bdec);
    for (int t = 0; t < NT; t++) {
        int gt = (t % 10) < 5;
        k_step<<<129, 256, STEP_SMEM>>>(t, gt, Wdec, bdec, out);
    }
    k_dec_final<<<33, 256>>>(Wdec, bdec, out);
}